// round 3
// baseline (speedup 1.0000x reference)
#include <cuda_runtime.h>

#define NB   8
#define NC   256
#define NH   128
#define NW   128
#define NG   32
#define CPG  8
#define NOUT 256
#define FEPS 1e-5f
#define HWSZ (NH * NW)

// Scratch (static __device__ globals are the sanctioned no-alloc workaround)
__device__ float g_y[(size_t)NB * NC * NH * NW];   // adaptive-conv output, 128 MiB
__device__ float g_mean[NB * NC];
__device__ float g_rstd[NB * NC];

__device__ __forceinline__ int refl(int i, int n) {
    return i < 0 ? -i : (i >= n ? 2 * n - 2 - i : i);
}

// ---- packed f32x2 helpers (Blackwell sm_103a) ----
__device__ __forceinline__ unsigned long long pack2(float lo, float hi) {
    unsigned long long r;
    asm("mov.b64 %0, {%1, %2};" : "=l"(r) : "f"(lo), "f"(hi));
    return r;
}
__device__ __forceinline__ unsigned long long fma2(unsigned long long a,
                                                   unsigned long long b,
                                                   unsigned long long c) {
    unsigned long long d;
    asm("fma.rn.f32x2 %0, %1, %2, %3;" : "=l"(d) : "l"(a), "l"(b), "l"(c));
    return d;
}
__device__ __forceinline__ float2 unpack2(unsigned long long v) {
    float2 f;
    asm("mov.b64 {%0, %1}, %2;" : "=f"(f.x), "=f"(f.y) : "l"(v));
    return f;
}

// ============================================================================
// Kernel 1: per-(b,c) mean / rstd over 128x128 (biased variance)
// ============================================================================
__global__ __launch_bounds__(256) void stats_kernel(const float* __restrict__ x) {
    __shared__ float sh[16];
    int bc = blockIdx.x;
    const float4* xc = reinterpret_cast<const float4*>(x + (size_t)bc * HWSZ);
    float s = 0.f, ss = 0.f;
    for (int i = threadIdx.x; i < HWSZ / 4; i += 256) {
        float4 v = xc[i];
        s  += (v.x + v.y) + (v.z + v.w);
        ss += (v.x * v.x + v.y * v.y) + (v.z * v.z + v.w * v.w);
    }
    #pragma unroll
    for (int o = 16; o > 0; o >>= 1) {
        s  += __shfl_down_sync(0xffffffffu, s,  o);
        ss += __shfl_down_sync(0xffffffffu, ss, o);
    }
    if ((threadIdx.x & 31) == 0) {
        sh[threadIdx.x >> 5]       = s;
        sh[8 + (threadIdx.x >> 5)] = ss;
    }
    __syncthreads();
    if (threadIdx.x == 0) {
        float S = 0.f, SS = 0.f;
        #pragma unroll
        for (int i = 0; i < 8; i++) { S += sh[i]; SS += sh[8 + i]; }
        float m   = S * (1.f / HWSZ);
        float var = SS * (1.f / HWSZ) - m * m;
        g_mean[bc] = m;
        g_rstd[bc] = rsqrtf(var + FEPS);
    }
}

// ============================================================================
// Kernel 2: fused instance-norm apply + adaptive grouped 3x3 + folded 1x1 + bias
// ============================================================================
__global__ __launch_bounds__(256, 2) void ada_kernel(
    const float* __restrict__ x,
    const float* __restrict__ ws,    // [B,C,CPG,3,3]
    const float* __restrict__ wp,    // [B,C,CPG,1,1]
    const float* __restrict__ bias)  // [B,C]
{
    __shared__ float tile[CPG][10][132];   // 8 ch x (8 rows + halo) x (128 + halo)
    __shared__ float sW[CPG][CPG][9];

    int rt = blockIdx.x;   // 0..15 (8-row tiles)
    int g  = blockIdx.y;
    int b  = blockIdx.z;
    int r0 = rt * 8;
    int t  = threadIdx.x;
    int cbase = b * NC + g * CPG;
    const float* xb = x + (size_t)cbase * HWSZ;

    // Fold pointwise into spatial: W[o][i][k] = sum_m wp[o][m] * ws[m][i][k]
    for (int e = t; e < CPG * CPG * 9; e += 256) {
        int o = e / 72, rem = e % 72, i = rem / 9, k = rem % 9;
        float acc = 0.f;
        #pragma unroll
        for (int m = 0; m < CPG; m++)
            acc += wp[(size_t)(cbase + o) * CPG + m] *
                   ws[((size_t)(cbase + m) * CPG + i) * 9 + k];
        sW[o][i][k] = acc;
    }

    // Load + normalize input tile with reflect padding
    for (int e = t; e < CPG * 10 * 130; e += 256) {
        int ch = e / 1300, rem = e % 1300, tr = rem / 130, tc = rem % 130;
        int gr = refl(r0 - 1 + tr, NH);
        int gc = refl(tc - 1, NW);
        float m  = g_mean[cbase + ch];
        float rs = g_rstd[cbase + ch];
        tile[ch][tr][tc] = (xb[(size_t)ch * HWSZ + gr * NW + gc] - m) * rs;
    }
    __syncthreads();

    int col = t & 127;
    int rq  = t >> 7;          // 0/1: which 4-row half
    float acc[CPG][4];
    #pragma unroll
    for (int o = 0; o < CPG; o++)
        #pragma unroll
        for (int r = 0; r < 4; r++) acc[o][r] = 0.f;

    #pragma unroll 1
    for (int i = 0; i < CPG; i++) {
        float v[6][3];
        #pragma unroll
        for (int rr = 0; rr < 6; rr++)
            #pragma unroll
            for (int c3 = 0; c3 < 3; c3++)
                v[rr][c3] = tile[i][rq * 4 + rr][col + c3];
        #pragma unroll
        for (int o = 0; o < CPG; o++) {
            #pragma unroll
            for (int k = 0; k < 9; k++) {
                float w = sW[o][i][k];
                int dy = k / 3, dx = k % 3;
                #pragma unroll
                for (int r = 0; r < 4; r++)
                    acc[o][r] += w * v[r + dy][dx];
            }
        }
    }

    #pragma unroll
    for (int o = 0; o < CPG; o++) {
        float bb = bias[cbase + o];
        #pragma unroll
        for (int r = 0; r < 4; r++)
            g_y[((size_t)(cbase + o) * NH + r0 + rq * 4 + r) * NW + col] = acc[o][r] + bb;
    }
}

// ============================================================================
// Kernel 3: final 3x3 conv 256->256 with reflect pad, fp32 via packed f32x2.
// Block = (b, 16 out-ch tile, 8-row tile). Input channels in chunks of 8.
// Thread: 1 col x 4 rows (2 f32x2 row-pairs) x 16 out channels.
// ============================================================================
#define CI_CHUNK 8
#define CO_TILE  16
#define CONV_TILE_FLOATS (CI_CHUNK * 10 * 132)
#define CONV_SMEM_BYTES  (CONV_TILE_FLOATS * 4 + CO_TILE * CI_CHUNK * 9 * 8)

extern __shared__ char s_conv[];

__global__ __launch_bounds__(256, 2) void conv_kernel(
    const float* __restrict__ conv_w,  // [OUT, C, 3, 3]
    const float* __restrict__ conv_b,  // [OUT]
    float* __restrict__ out)
{
    float* tile = reinterpret_cast<float*>(s_conv);
    unsigned long long* sw2 =
        reinterpret_cast<unsigned long long*>(s_conv + CONV_TILE_FLOATS * 4);

    int rt  = blockIdx.x;   // 0..15
    int cot = blockIdx.y;   // 0..15
    int b   = blockIdx.z;
    int r0  = rt * 8;
    int co0 = cot * CO_TILE;
    int t   = threadIdx.x;
    int col = t & 127;
    int rq  = t >> 7;       // 0/1

    unsigned long long acc2[CO_TILE][2];
    #pragma unroll
    for (int co = 0; co < CO_TILE; co++) { acc2[co][0] = 0ull; acc2[co][1] = 0ull; }

    #pragma unroll 1
    for (int q = 0; q < NC / CI_CHUNK; q++) {
        // Stage input tile (8 ci x 10 rows x 130 cols, reflect-padded) from g_y
        for (int e = t; e < CI_CHUNK * 10 * 130; e += 256) {
            int ch = e / 1300, rem = e % 1300, tr = rem / 130, tc = rem % 130;
            int gr = refl(r0 - 1 + tr, NH);
            int gc = refl(tc - 1, NW);
            tile[(ch * 10 + tr) * 132 + tc] =
                g_y[(((size_t)b * NC + q * CI_CHUNK + ch) * NH + gr) * NW + gc];
        }
        // Stage weights, pre-packed {w, w}
        for (int e = t; e < CO_TILE * CI_CHUNK * 9; e += 256) {
            int co_l = e / 72, rem = e % 72, ci_l = rem / 9, k = rem % 9;
            float w = conv_w[((size_t)(co0 + co_l) * NC + q * CI_CHUNK + ci_l) * 9 + k];
            sw2[e] = pack2(w, w);
        }
        __syncthreads();

        #pragma unroll 1
        for (int ci = 0; ci < CI_CHUNK; ci++) {
            float v[6][3];
            #pragma unroll
            for (int rr = 0; rr < 6; rr++)
                #pragma unroll
                for (int c3 = 0; c3 < 3; c3++)
                    v[rr][c3] = tile[(ci * 10 + rq * 4 + rr) * 132 + col + c3];
            unsigned long long v2[5][3];
            #pragma unroll
            for (int rr = 0; rr < 5; rr++)
                #pragma unroll
                for (int c3 = 0; c3 < 3; c3++)
                    v2[rr][c3] = pack2(v[rr][c3], v[rr + 1][c3]);

            #pragma unroll
            for (int co = 0; co < CO_TILE; co++) {
                #pragma unroll
                for (int k = 0; k < 9; k++) {
                    unsigned long long w2 = sw2[(co * CI_CHUNK + ci) * 9 + k];
                    int dy = k / 3, dx = k % 3;
                    acc2[co][0] = fma2(w2, v2[dy][dx],     acc2[co][0]);
                    acc2[co][1] = fma2(w2, v2[dy + 2][dx], acc2[co][1]);
                }
            }
        }
        __syncthreads();
    }

    #pragma unroll
    for (int co = 0; co < CO_TILE; co++) {
        float cb = conv_b[co0 + co];
        float2 p0 = unpack2(acc2[co][0]);
        float2 p1 = unpack2(acc2[co][1]);
        size_t base = (((size_t)b * NOUT + co0 + co) * NH + r0 + rq * 4) * NW + col;
        out[base]          = p0.x + cb;
        out[base + NW]     = p0.y + cb;
        out[base + 2 * NW] = p1.x + cb;
        out[base + 3 * NW] = p1.y + cb;
    }
}

// ============================================================================
extern "C" void kernel_launch(void* const* d_in, const int* in_sizes, int n_in,
                              void* d_out, int out_size) {
    const float* x      = (const float*)d_in[0];
    const float* ws     = (const float*)d_in[1];
    const float* wp     = (const float*)d_in[2];
    const float* bias   = (const float*)d_in[3];
    const float* conv_w = (const float*)d_in[4];
    const float* conv_b = (const float*)d_in[5];
    float* out = (float*)d_out;

    stats_kernel<<<NB * NC, 256>>>(x);
    ada_kernel<<<dim3(16, NG, NB), 256>>>(x, ws, wp, bias);

    cudaFuncSetAttribute(conv_kernel,
                         cudaFuncAttributeMaxDynamicSharedMemorySize,
                         CONV_SMEM_BYTES);
    conv_kernel<<<dim3(16, 16, NB), 256, CONV_SMEM_BYTES>>>(conv_w, conv_b, out);
}

// round 6
// speedup vs baseline: 3.1180x; 3.1180x over previous
#include <cuda_runtime.h>
#include <cuda_bf16.h>
#include <cstdint>

#define NB   8
#define NC   256
#define NH   128
#define NW   128
#define NG   32
#define CPG  8
#define NOUT 256
#define FEPS 1e-5f
#define HWSZ (NH * NW)

// ---------------- device scratch (no-alloc rule: __device__ globals) --------
// y split into bf16 hi/lo, packed as channel PAIRS: u32 = {bf16(c even) lo16, bf16(c odd) hi16}
// layout [b][c2=0..127][pix]
__device__ uint32_t g_yh2[(size_t)NB * 128 * HWSZ];
__device__ uint32_t g_yl2[(size_t)NB * 128 * HWSZ];
__device__ float    g_mean[NB * NC];
__device__ float    g_rstd[NB * NC];
// conv weights hi/lo, ci-pair packed: layout [tap][ci2=0..127][co=0..255]
__device__ uint32_t g_wh2[9 * 128 * 256];
__device__ uint32_t g_wl2[9 * 128 * 256];

__device__ __forceinline__ int refl(int i, int n) {
    return i < 0 ? -i : (i >= n ? 2 * n - 2 - i : i);
}

__device__ __forceinline__ void mma16816(float* c, const uint32_t* a,
                                         uint32_t b0, uint32_t b1) {
    asm volatile(
        "mma.sync.aligned.m16n8k16.row.col.f32.bf16.bf16.f32 "
        "{%0,%1,%2,%3}, {%4,%5,%6,%7}, {%8,%9}, {%0,%1,%2,%3};"
        : "+f"(c[0]), "+f"(c[1]), "+f"(c[2]), "+f"(c[3])
        : "r"(a[0]), "r"(a[1]), "r"(a[2]), "r"(a[3]), "r"(b0), "r"(b1));
}

// ============================================================================
// Kernel 1: per-(b,c) mean / rstd over 128x128 (biased variance)
// ============================================================================
__global__ __launch_bounds__(256) void stats_kernel(const float* __restrict__ x) {
    __shared__ float sh[16];
    int bc = blockIdx.x;
    const float4* xc = reinterpret_cast<const float4*>(x + (size_t)bc * HWSZ);
    float s = 0.f, ss = 0.f;
    for (int i = threadIdx.x; i < HWSZ / 4; i += 256) {
        float4 v = xc[i];
        s  += (v.x + v.y) + (v.z + v.w);
        ss += (v.x * v.x + v.y * v.y) + (v.z * v.z + v.w * v.w);
    }
    #pragma unroll
    for (int o = 16; o > 0; o >>= 1) {
        s  += __shfl_down_sync(0xffffffffu, s,  o);
        ss += __shfl_down_sync(0xffffffffu, ss, o);
    }
    if ((threadIdx.x & 31) == 0) {
        sh[threadIdx.x >> 5]       = s;
        sh[8 + (threadIdx.x >> 5)] = ss;
    }
    __syncthreads();
    if (threadIdx.x == 0) {
        float S = 0.f, SS = 0.f;
        #pragma unroll
        for (int i = 0; i < 8; i++) { S += sh[i]; SS += sh[8 + i]; }
        float m   = S * (1.f / HWSZ);
        float var = SS * (1.f / HWSZ) - m * m;
        g_mean[bc] = m;
        g_rstd[bc] = rsqrtf(var + FEPS);
    }
}

// ============================================================================
// Kernel 1b: split + ci-pair-pack final-conv weights -> g_wh2/g_wl2
// ============================================================================
__global__ __launch_bounds__(256) void wprep_kernel(const float* __restrict__ conv_w) {
    int tap = blockIdx.x;   // 0..8
    for (int e = threadIdx.x; e < 128 * 256; e += 256) {
        int ci2 = e >> 8, co = e & 255;
        float w0 = conv_w[((size_t)co * NC + 2 * ci2)     * 9 + tap];
        float w1 = conv_w[((size_t)co * NC + 2 * ci2 + 1) * 9 + tap];
        __nv_bfloat16 h0 = __float2bfloat16(w0);
        __nv_bfloat16 h1 = __float2bfloat16(w1);
        __nv_bfloat16 l0 = __float2bfloat16(w0 - __bfloat162float(h0));
        __nv_bfloat16 l1 = __float2bfloat16(w1 - __bfloat162float(h1));
        size_t idx = (size_t)(tap * 128 + ci2) * 256 + co;
        g_wh2[idx] = (uint32_t)__bfloat16_as_ushort(h0) |
                     ((uint32_t)__bfloat16_as_ushort(h1) << 16);
        g_wl2[idx] = (uint32_t)__bfloat16_as_ushort(l0) |
                     ((uint32_t)__bfloat16_as_ushort(l1) << 16);
    }
}

// ============================================================================
// Kernel 2: fused instance-norm + adaptive grouped 3x3 + folded 1x1 + bias,
//           emitting channel-pair-packed bf16 hi/lo arrays.
// ============================================================================
__global__ __launch_bounds__(256, 2) void ada_kernel(
    const float* __restrict__ x,
    const float* __restrict__ ws,    // [B,C,CPG,3,3]
    const float* __restrict__ wp,    // [B,C,CPG,1,1]
    const float* __restrict__ bias)  // [B,C]
{
    __shared__ float tile[CPG][10][132];
    __shared__ float sW[CPG][CPG][9];

    int rt = blockIdx.x;   // 0..15
    int g  = blockIdx.y;
    int b  = blockIdx.z;
    int r0 = rt * 8;
    int t  = threadIdx.x;
    int cbase = b * NC + g * CPG;
    const float* xb = x + (size_t)cbase * HWSZ;

    for (int e = t; e < CPG * CPG * 9; e += 256) {
        int o = e / 72, rem = e % 72, i = rem / 9, k = rem % 9;
        float acc = 0.f;
        #pragma unroll
        for (int m = 0; m < CPG; m++)
            acc += wp[(size_t)(cbase + o) * CPG + m] *
                   ws[((size_t)(cbase + m) * CPG + i) * 9 + k];
        sW[o][i][k] = acc;
    }

    for (int e = t; e < CPG * 10 * 130; e += 256) {
        int ch = e / 1300, rem = e % 1300, tr = rem / 130, tc = rem % 130;
        int gr = refl(r0 - 1 + tr, NH);
        int gc = refl(tc - 1, NW);
        float m  = g_mean[cbase + ch];
        float rs = g_rstd[cbase + ch];
        tile[ch][tr][tc] = (xb[(size_t)ch * HWSZ + gr * NW + gc] - m) * rs;
    }
    __syncthreads();

    int col = t & 127;
    int rq  = t >> 7;
    float acc[CPG][4];
    #pragma unroll
    for (int o = 0; o < CPG; o++)
        #pragma unroll
        for (int r = 0; r < 4; r++) acc[o][r] = 0.f;

    #pragma unroll 1
    for (int i = 0; i < CPG; i++) {
        float v[6][3];
        #pragma unroll
        for (int rr = 0; rr < 6; rr++)
            #pragma unroll
            for (int c3 = 0; c3 < 3; c3++)
                v[rr][c3] = tile[i][rq * 4 + rr][col + c3];
        #pragma unroll
        for (int o = 0; o < CPG; o++) {
            #pragma unroll
            for (int k = 0; k < 9; k++) {
                float w = sW[o][i][k];
                int dy = k / 3, dx = k % 3;
                #pragma unroll
                for (int r = 0; r < 4; r++)
                    acc[o][r] += w * v[r + dy][dx];
            }
        }
    }

    int ccg = g * CPG;   // channel base within batch
    #pragma unroll
    for (int o = 0; o < CPG; o += 2) {
        float b0v = bias[cbase + o], b1v = bias[cbase + o + 1];
        int c2 = (ccg + o) >> 1;
        #pragma unroll
        for (int r = 0; r < 4; r++) {
            float v0 = acc[o][r] + b0v;
            float v1 = acc[o + 1][r] + b1v;
            __nv_bfloat16 h0 = __float2bfloat16(v0);
            __nv_bfloat16 h1 = __float2bfloat16(v1);
            __nv_bfloat16 l0 = __float2bfloat16(v0 - __bfloat162float(h0));
            __nv_bfloat16 l1 = __float2bfloat16(v1 - __bfloat162float(h1));
            size_t idx = ((size_t)(b * 128 + c2)) * HWSZ +
                         (size_t)(r0 + rq * 4 + r) * NW + col;
            g_yh2[idx] = (uint32_t)__bfloat16_as_ushort(h0) |
                         ((uint32_t)__bfloat16_as_ushort(h1) << 16);
            g_yl2[idx] = (uint32_t)__bfloat16_as_ushort(l0) |
                         ((uint32_t)__bfloat16_as_ushort(l1) << 16);
        }
    }
}

// ============================================================================
// Kernel 3: final 3x3 conv 256->256 via mma.sync.m16n8k16 bf16, 3-term split.
// CTA = (output row r, co-half, batch). D[m=128 pixels][n=128 co].
// A: im2col tile per 32-ci chunk: [16 c2][3 rows][130 cols+pad2], reused by
//    all 9 taps via (dy,dx) offsets. B: 16KB linear copy per (tap,chunk).
// Warp layout: 8 warps = 4(M) x 2(N); warp tile M=32 x N=64.
// ============================================================================
#define A_WORDS   6336            // 16 * 396
#define B_WORDS   2112            // 16 * 132
#define CONV_SMEM ((2 * A_WORDS + 2 * B_WORDS) * 4)   // 67584 bytes

extern __shared__ uint32_t s_cv[];

__global__ __launch_bounds__(256, 2) void conv_mma_kernel(
    const float* __restrict__ conv_b,
    float* __restrict__ out)
{
    uint32_t* Ah = s_cv;
    uint32_t* Al = s_cv + A_WORDS;
    uint32_t* Bh = s_cv + 2 * A_WORDS;
    uint32_t* Bl = s_cv + 2 * A_WORDS + B_WORDS;
    float*    S  = reinterpret_cast<float*>(s_cv);   // epilogue reuse: 128*130 floats

    int t = threadIdx.x, l = t & 31, wid = t >> 5;
    int r    = blockIdx.x;        // output row
    int half = blockIdx.y;        // co half
    int b    = blockIdx.z;
    int co0  = half * 128;
    int m0   = (wid & 3) * 32;
    int n0   = (wid >> 2) * 64;
    int k2l  = l & 3;
    int lq   = l >> 2;

    float acc[2][8][4];
    #pragma unroll
    for (int mt = 0; mt < 2; mt++)
        #pragma unroll
        for (int nt = 0; nt < 8; nt++)
            #pragma unroll
            for (int i = 0; i < 4; i++) acc[mt][nt][i] = 0.f;

    #pragma unroll 1
    for (int chunk = 0; chunk < 8; chunk++) {
        __syncthreads();   // previous iteration's reads complete
        // ---- stage A: 16 c2 x 3 rows x 130 cols (hi & lo) ----
        for (int e = t; e < 16 * 3 * 130; e += 256) {
            int c2 = e / 390, rem = e % 390;
            int row = rem / 130, mc = rem % 130;
            int gr = refl(r - 1 + row, NH);
            int gc = refl(mc - 1, NW);
            size_t src = ((size_t)(b * 128 + chunk * 16 + c2)) * HWSZ +
                         (size_t)gr * NW + gc;
            int dst = c2 * 396 + row * 132 + mc;
            Ah[dst] = g_yh2[src];
            Al[dst] = g_yl2[src];
        }

        #pragma unroll 1
        for (int tap = 0; tap < 9; tap++) {
            if (tap > 0) __syncthreads();   // previous B reads complete
            // ---- stage B: 16 c2 x 128 co (hi & lo), linear uint4 copy ----
            {
                const uint4* srcH = reinterpret_cast<const uint4*>(
                    g_wh2 + (size_t)(tap * 128 + chunk * 16) * 256 + co0);
                const uint4* srcL = reinterpret_cast<const uint4*>(
                    g_wl2 + (size_t)(tap * 128 + chunk * 16) * 256 + co0);
                for (int i = t; i < 512; i += 256) {
                    int row = i >> 5, c4 = i & 31;
                    reinterpret_cast<uint4*>(Bh + row * 132)[c4] = srcH[row * 64 + c4];
                    reinterpret_cast<uint4*>(Bl + row * 132)[c4] = srcL[row * 64 + c4];
                }
            }
            __syncthreads();   // A (tap 0) + B visible

            int dy = tap / 3 - 1, dx = tap % 3 - 1;
            int aoff = (1 + dy) * 132 + 1 + dx;

            #pragma unroll
            for (int kk = 0; kk < 2; kk++) {
                int c2b = kk * 8 + k2l;
                uint32_t ah[2][4], al[2][4];
                #pragma unroll
                for (int mt = 0; mt < 2; mt++) {
                    int mrow = m0 + mt * 16 + lq;
                    int b0i = c2b * 396 + aoff + mrow;
                    int b1i = (c2b + 4) * 396 + aoff + mrow;
                    ah[mt][0] = Ah[b0i];     ah[mt][1] = Ah[b0i + 8];
                    ah[mt][2] = Ah[b1i];     ah[mt][3] = Ah[b1i + 8];
                    al[mt][0] = Al[b0i];     al[mt][1] = Al[b0i + 8];
                    al[mt][2] = Al[b1i];     al[mt][3] = Al[b1i + 8];
                }
                #pragma unroll
                for (int nt = 0; nt < 8; nt++) {
                    int n = n0 + nt * 8 + lq;
                    int bb0 = c2b * 132 + n;
                    int bb1 = (c2b + 4) * 132 + n;
                    uint32_t bh0 = Bh[bb0], bh1 = Bh[bb1];
                    uint32_t bl0 = Bl[bb0], bl1 = Bl[bb1];
                    #pragma unroll
                    for (int mt = 0; mt < 2; mt++) {
                        mma16816(acc[mt][nt], ah[mt], bh0, bh1);  // yh*wh
                        mma16816(acc[mt][nt], al[mt], bh0, bh1);  // yl*wh
                        mma16816(acc[mt][nt], ah[mt], bl0, bl1);  // yh*wl
                    }
                }
            }
        }
    }

    // ---- epilogue: fragments -> smem [n][130+m] -> coalesced GMEM + bias ----
    __syncthreads();
    #pragma unroll
    for (int mt = 0; mt < 2; mt++) {
        #pragma unroll
        for (int nt = 0; nt < 8; nt++) {
            int m = m0 + mt * 16 + lq;
            int n = n0 + nt * 8 + 2 * k2l;
            S[n * 130 + m]           = acc[mt][nt][0];
            S[(n + 1) * 130 + m]     = acc[mt][nt][1];
            S[n * 130 + m + 8]       = acc[mt][nt][2];
            S[(n + 1) * 130 + m + 8] = acc[mt][nt][3];
        }
    }
    __syncthreads();
    for (int e = t; e < 128 * 128; e += 256) {
        int n = e >> 7, m = e & 127;
        out[((size_t)(b * NOUT + co0 + n)) * HWSZ + (size_t)r * NW + m] =
            S[n * 130 + m] + conv_b[co0 + n];
    }
}

// ============================================================================
extern "C" void kernel_launch(void* const* d_in, const int* in_sizes, int n_in,
                              void* d_out, int out_size) {
    const float* x      = (const float*)d_in[0];
    const float* ws     = (const float*)d_in[1];
    const float* wp     = (const float*)d_in[2];
    const float* bias   = (const float*)d_in[3];
    const float* conv_w = (const float*)d_in[4];
    const float* conv_b = (const float*)d_in[5];
    float* out = (float*)d_out;

    stats_kernel<<<NB * NC, 256>>>(x);
    wprep_kernel<<<9, 256>>>(conv_w);
    ada_kernel<<<dim3(16, NG, NB), 256>>>(x, ws, wp, bias);

    cudaFuncSetAttribute(conv_mma_kernel,
                         cudaFuncAttributeMaxDynamicSharedMemorySize,
                         CONV_SMEM);
    conv_mma_kernel<<<dim3(NH, 2, NB), 256, CONV_SMEM>>>(conv_b, out);
}